// round 2
// baseline (speedup 1.0000x reference)
#include <cuda_runtime.h>
#include <cuda_bf16.h>
#include <math.h>

#define N 8192
#define D 128
#define BM 128
#define BN 128
#define NTHREADS 256

// scratch (device globals: allocation-free)
__device__ __align__(16) float g_embT[D * N];   // [k][j]  4 MB
__device__ float g_sq[N];
__device__ int   g_lab[N];
__device__ int   g_pos[N];   // max d^2 over same-label (float bits)
__device__ int   g_neg[N];   // min d^2 over diff-label (float bits)

// ---------------------------------------------------------------------------
// 0) normalize labels: handles int32 OR int64 input layout.
//    int64 little-endian with values < 512 -> every odd 32-bit word is 0.
// ---------------------------------------------------------------------------
__global__ void k_labels(const int* __restrict__ lab32) {
    __shared__ int stride;
    if (threadIdx.x == 0) {
        int s = 2;                       // assume int64
        for (int i = 1; i < 128; i += 2)
            if (lab32[i] != 0) { s = 1; break; }   // found nonzero odd word -> int32
        stride = s;
    }
    __syncthreads();
    int i = blockIdx.x * blockDim.x + threadIdx.x;
    if (i < N) g_lab[i] = lab32[i * stride];
}

// ---------------------------------------------------------------------------
// 1) transpose emb[N][D] -> embT[D][N]
// ---------------------------------------------------------------------------
__global__ void k_transpose(const float* __restrict__ emb) {
    __shared__ float tile[32][33];
    int j0 = blockIdx.x * 32;   // row block in emb
    int k0 = blockIdx.y * 32;   // col block in emb
    int x = threadIdx.x, y = threadIdx.y;   // 32 x 8
#pragma unroll
    for (int i = 0; i < 32; i += 8)
        tile[y + i][x] = emb[(size_t)(j0 + y + i) * D + k0 + x];
    __syncthreads();
#pragma unroll
    for (int i = 0; i < 32; i += 8)
        g_embT[(size_t)(k0 + y + i) * N + j0 + x] = tile[x][y + i];
}

// ---------------------------------------------------------------------------
// 2) per-row squared norms + init reductions
// ---------------------------------------------------------------------------
__global__ void k_sqinit(const float* __restrict__ emb) {
    int warp = threadIdx.x >> 5;
    int lane = threadIdx.x & 31;
    int row = blockIdx.x * 8 + warp;   // 1024 blocks x 8 warps
    float4 v = reinterpret_cast<const float4*>(emb)[row * 32 + lane];
    float s = v.x * v.x + v.y * v.y + v.z * v.z + v.w * v.w;
#pragma unroll
    for (int o = 16; o > 0; o >>= 1)
        s += __shfl_xor_sync(0xffffffffu, s, o);
    if (lane == 0) {
        g_sq[row]  = s;
        g_pos[row] = 0;                    // 0.0f
        g_neg[row] = 0x7f800000;           // +inf
    }
}

// ---------------------------------------------------------------------------
// 3) fused distance-GEMM + hardest pos/neg reduction
//    grid (64, 8): blockIdx.x = i-tile, blockIdx.y picks 8 j-tiles
// ---------------------------------------------------------------------------
__global__ void __launch_bounds__(NTHREADS)
k_main() {
    extern __shared__ float smem[];
    float* As  = smem;                       // [128][128] k-major
    float* Bs  = smem + BM * D;              // [128][128] k-major
    float* sqI = Bs + BN * D;                // 128
    float* sqJ = sqI + 128;                  // 128
    int*   labI = (int*)(sqJ + 128);         // 128
    int*   labJ = labI + 128;                // 128

    const int tid = threadIdx.x;
    const int tx  = tid & 15;
    const int ty  = tid >> 4;
    const int i0  = blockIdx.x * BM;

    // load A tile (k-major, conflict-free float4)
#pragma unroll
    for (int q = 0; q < 16; q++) {
        int idx = q * NTHREADS + tid;        // 0..4095 float4s
        int k = idx >> 5, i4 = idx & 31;
        reinterpret_cast<float4*>(As)[k * 32 + i4] =
            *reinterpret_cast<const float4*>(&g_embT[(size_t)k * N + i0 + i4 * 4]);
    }
    if (tid < 128) {
        sqI[tid]  = g_sq[i0 + tid];
        labI[tid] = g_lab[i0 + tid];
    }

    float pmax[8], nmin[8];
#pragma unroll
    for (int r = 0; r < 8; r++) { pmax[r] = 0.0f; nmin[r] = __int_as_float(0x7f800000); }

    for (int t = 0; t < 8; t++) {
        const int j0 = (blockIdx.y * 8 + t) * BN;
        __syncthreads();   // protect Bs from previous iteration's readers
#pragma unroll
        for (int q = 0; q < 16; q++) {
            int idx = q * NTHREADS + tid;
            int k = idx >> 5, j4 = idx & 31;
            reinterpret_cast<float4*>(Bs)[k * 32 + j4] =
                *reinterpret_cast<const float4*>(&g_embT[(size_t)k * N + j0 + j4 * 4]);
        }
        if (tid < 128) {
            sqJ[tid]  = g_sq[j0 + tid];
            labJ[tid] = g_lab[j0 + tid];
        }
        __syncthreads();

        float acc[8][8];
#pragma unroll
        for (int r = 0; r < 8; r++)
#pragma unroll
            for (int s = 0; s < 8; s++) acc[r][s] = 0.0f;

#pragma unroll 8
        for (int k = 0; k < D; k++) {
            float4 a0 = *reinterpret_cast<float4*>(&As[k * BM + ty * 8]);
            float4 a1 = *reinterpret_cast<float4*>(&As[k * BM + ty * 8 + 4]);
            float4 b0 = *reinterpret_cast<float4*>(&Bs[k * BN + tx * 8]);
            float4 b1 = *reinterpret_cast<float4*>(&Bs[k * BN + tx * 8 + 4]);
            float a[8] = {a0.x, a0.y, a0.z, a0.w, a1.x, a1.y, a1.z, a1.w};
            float b[8] = {b0.x, b0.y, b0.z, b0.w, b1.x, b1.y, b1.z, b1.w};
#pragma unroll
            for (int r = 0; r < 8; r++)
#pragma unroll
                for (int s = 0; s < 8; s++)
                    acc[r][s] = fmaf(a[r], b[s], acc[r][s]);
        }

        // epilogue: d^2 = sqI + sqJ - 2*dot ; hardest pos/neg on d^2
#pragma unroll
        for (int r = 0; r < 8; r++) {
            float si = sqI[ty * 8 + r];
            int   li = labI[ty * 8 + r];
#pragma unroll
            for (int s = 0; s < 8; s++) {
                float d2 = si + sqJ[tx * 8 + s] - 2.0f * acc[r][s];
                d2 = fmaxf(d2, 0.0f);
                if (li == labJ[tx * 8 + s]) pmax[r] = fmaxf(pmax[r], d2);
                else                        nmin[r] = fminf(nmin[r], d2);
            }
        }
    }

    // reduce across tx (16 lanes per half-warp share the same 8 rows)
#pragma unroll
    for (int r = 0; r < 8; r++) {
        float p = pmax[r], n = nmin[r];
#pragma unroll
        for (int o = 8; o > 0; o >>= 1) {
            p = fmaxf(p, __shfl_xor_sync(0xffffffffu, p, o));
            n = fminf(n, __shfl_xor_sync(0xffffffffu, n, o));
        }
        if (tx == 0) {
            int gi = i0 + ty * 8 + r;
            atomicMax(&g_pos[gi], __float_as_int(p));
            atomicMin(&g_neg[gi], __float_as_int(n));
        }
    }
}

// ---------------------------------------------------------------------------
// 4) finalize: mean(relu(sqrt(pos) - sqrt(neg) + margin))
// ---------------------------------------------------------------------------
__global__ void k_final(const float* __restrict__ margin, float* __restrict__ out) {
    __shared__ float red[NTHREADS];
    float m = *margin;
    float sum = 0.0f;
    for (int i = threadIdx.x; i < N; i += NTHREADS) {
        float p = sqrtf(__int_as_float(g_pos[i]));
        float n = sqrtf(__int_as_float(g_neg[i]));
        sum += fmaxf(p - n + m, 0.0f);
    }
    red[threadIdx.x] = sum;
    __syncthreads();
#pragma unroll
    for (int s = NTHREADS / 2; s > 0; s >>= 1) {
        if (threadIdx.x < s) red[threadIdx.x] += red[threadIdx.x + s];
        __syncthreads();
    }
    if (threadIdx.x == 0) out[0] = red[0] / (float)N;
}

// ---------------------------------------------------------------------------
extern "C" void kernel_launch(void* const* d_in, const int* in_sizes, int n_in,
                              void* d_out, int out_size) {
    const float* emb    = (const float*)d_in[0];
    const int*   lab32  = (const int*)d_in[1];
    const float* margin = (const float*)d_in[2];
    float*       out    = (float*)d_out;

    const int smem_bytes = (BM * D + BN * D + 128 + 128) * 4 + 128 * 4 * 2;  // 133120
    cudaFuncSetAttribute(k_main, cudaFuncAttributeMaxDynamicSharedMemorySize, smem_bytes);

    k_labels<<<N / 256, 256>>>(lab32);
    k_transpose<<<dim3(N / 32, D / 32), dim3(32, 8)>>>(emb);
    k_sqinit<<<N / 8, 256>>>(emb);
    k_main<<<dim3(N / BM, (N / BN) / 8), NTHREADS, smem_bytes>>>();
    k_final<<<1, NTHREADS>>>(margin, out);
}

// round 4
// speedup vs baseline: 3.0663x; 3.0663x over previous
#include <cuda_runtime.h>
#include <cuda_bf16.h>
#include <math.h>
#include <stdint.h>

#define N 8192
#define D 128
#define TILE 128
#define NT 256
#define T_PER 32
#define S 132                    // smem row stride in floats (pad 4 -> conflict-free frags)

#define A_OFF 0
#define B_OFF(b) (TILE * S + (b) * TILE * S)   // A: 128*132 floats, then 2 B buffers
#define SMEM_FLOATS (3 * TILE * S)
#define SMEM_BYTES  (SMEM_FLOATS * 4)          // 202752

static __device__ __align__(16) float g_embR[N * D];  // tf32-rounded, 4 MB
static __device__ float g_sq[N];
static __device__ int   g_lab[N];
static __device__ int   g_pos[N];
static __device__ int   g_neg[N];

// ---------------------------------------------------------------------------
// 0) labels: handle int32 OR int64 buffer layout (probe odd words)
// ---------------------------------------------------------------------------
__global__ void k_labels(const int* __restrict__ lab32) {
    __shared__ int stride;
    if (threadIdx.x == 0) {
        int s = 2;
        for (int i = 1; i < 128; i += 2)
            if (lab32[i] != 0) { s = 1; break; }
        stride = s;
    }
    __syncthreads();
    int i = blockIdx.x * blockDim.x + threadIdx.x;
    if (i < N) g_lab[i] = lab32[i * stride];
}

// ---------------------------------------------------------------------------
// 1) prep: tf32-round embeddings; norms of the ROUNDED copy; init reductions
// ---------------------------------------------------------------------------
__global__ void k_prep(const float* __restrict__ emb) {
    int warp = threadIdx.x >> 5, lane = threadIdx.x & 31;
    int row = blockIdx.x * 8 + warp;
    float4 v = reinterpret_cast<const float4*>(emb)[row * 32 + lane];
    float4 r;
    asm("cvt.rna.tf32.f32 %0, %1;" : "=f"(r.x) : "f"(v.x));
    asm("cvt.rna.tf32.f32 %0, %1;" : "=f"(r.y) : "f"(v.y));
    asm("cvt.rna.tf32.f32 %0, %1;" : "=f"(r.z) : "f"(v.z));
    asm("cvt.rna.tf32.f32 %0, %1;" : "=f"(r.w) : "f"(v.w));
    float s = r.x * r.x + r.y * r.y + r.z * r.z + r.w * r.w;
#pragma unroll
    for (int o = 16; o > 0; o >>= 1) s += __shfl_xor_sync(0xffffffffu, s, o);
    reinterpret_cast<float4*>(g_embR)[row * 32 + lane] = r;
    if (lane == 0) {
        g_sq[row]  = s;
        g_pos[row] = 0;
        g_neg[row] = 0x7f800000;
    }
}

// ---------------------------------------------------------------------------
// 2) main: mma.sync tf32 d^2-GEMM + fused hardest pos/neg reduction
//    grid (64, 2): x = i-tile, y = j-half (32 j-tiles per CTA)
// ---------------------------------------------------------------------------
__global__ void __launch_bounds__(NT) k_main() {
    extern __shared__ float smem[];
    const int tid  = threadIdx.x;
    const int wid  = tid >> 5;
    const int lane = tid & 31;
    const int wm   = wid & 3;        // warp row  (4 along M)
    const int wn   = wid >> 2;       // warp col  (2 along N)
    const int g    = lane >> 2;      // group id
    const int tg   = lane & 3;       // thread-in-group
    const int i0    = blockIdx.x * TILE;
    const int jbase = blockIdx.y * T_PER * TILE;

    // ---- prologue: A tile + B(0) via cp.async ----
#pragma unroll
    for (int q = 0; q < 16; q++) {
        int idx = q * NT + tid;              // 0..4095
        int row = idx >> 5, ch = idx & 31;   // 32 float4 chunks per row
        uint32_t dstA = __cvta_generic_to_shared(&smem[A_OFF + row * S + ch * 4]);
        uint32_t dstB = __cvta_generic_to_shared(&smem[B_OFF(0) + row * S + ch * 4]);
        const float* srcA = g_embR + (size_t)(i0 + row) * D + ch * 4;
        const float* srcB = g_embR + (size_t)(jbase + row) * D + ch * 4;
        asm volatile("cp.async.cg.shared.global [%0], [%1], 16;" :: "r"(dstA), "l"(srcA));
        asm volatile("cp.async.cg.shared.global [%0], [%1], 16;" :: "r"(dstB), "l"(srcB));
    }
    asm volatile("cp.async.commit_group;");

    // ---- per-thread row metadata (4 row slots: (mt,h) -> wm*32+mt*16+h*8+g) ----
    float sI[4]; int lI[4];
    float pm[4], nm[4];
#pragma unroll
    for (int ridx = 0; ridx < 4; ridx++) {
        int row = i0 + wm * 32 + (ridx >> 1) * 16 + (ridx & 1) * 8 + g;
        sI[ridx] = g_sq[row];
        lI[ridx] = g_lab[row];
        pm[ridx] = 0.0f;
        nm[ridx] = __int_as_float(0x7f800000);
    }

    for (int tt = 0; tt < T_PER; tt++) {
        // start B(tt+1) loads (overlaps with the wait + compute of tile tt)
        if (tt + 1 < T_PER) {
            const int nb = (tt + 1) & 1;
#pragma unroll
            for (int q = 0; q < 16; q++) {
                int idx = q * NT + tid;
                int row = idx >> 5, ch = idx & 31;
                uint32_t dst = __cvta_generic_to_shared(&smem[B_OFF(nb) + row * S + ch * 4]);
                const float* src = g_embR + (size_t)(jbase + (tt + 1) * TILE + row) * D + ch * 4;
                asm volatile("cp.async.cg.shared.global [%0], [%1], 16;" :: "r"(dst), "l"(src));
            }
            asm volatile("cp.async.commit_group;");
            asm volatile("cp.async.wait_group 1;" ::: "memory");
        } else {
            asm volatile("cp.async.wait_group 0;" ::: "memory");
        }
        __syncthreads();   // B(tt) visible to everyone

        // ---- 16 k-steps of m16n8k8 tf32 mma ----
        float acc[2][8][4];
#pragma unroll
        for (int mt = 0; mt < 2; mt++)
#pragma unroll
            for (int nt = 0; nt < 8; nt++)
#pragma unroll
                for (int c = 0; c < 4; c++) acc[mt][nt][c] = 0.0f;

        const uint32_t* Au = (const uint32_t*)(smem + A_OFF);
        const uint32_t* Bu = (const uint32_t*)(smem + B_OFF(tt & 1));

#pragma unroll
        for (int ks = 0; ks < 16; ks++) {
            const int k0 = ks * 8;
            uint32_t a[2][4];
#pragma unroll
            for (int mt = 0; mt < 2; mt++) {
                int rb = wm * 32 + mt * 16 + g;
                a[mt][0] = Au[rb * S + k0 + tg];
                a[mt][1] = Au[(rb + 8) * S + k0 + tg];
                a[mt][2] = Au[rb * S + k0 + tg + 4];
                a[mt][3] = Au[(rb + 8) * S + k0 + tg + 4];
            }
            uint32_t b[8][2];
#pragma unroll
            for (int nt = 0; nt < 8; nt++) {
                int nb = wn * 64 + nt * 8 + g;
                b[nt][0] = Bu[nb * S + k0 + tg];
                b[nt][1] = Bu[nb * S + k0 + tg + 4];
            }
#pragma unroll
            for (int mt = 0; mt < 2; mt++)
#pragma unroll
                for (int nt = 0; nt < 8; nt++) {
                    asm volatile(
                        "mma.sync.aligned.m16n8k8.row.col.f32.tf32.tf32.f32 "
                        "{%0,%1,%2,%3}, {%4,%5,%6,%7}, {%8,%9}, {%0,%1,%2,%3};"
                        : "+f"(acc[mt][nt][0]), "+f"(acc[mt][nt][1]),
                          "+f"(acc[mt][nt][2]), "+f"(acc[mt][nt][3])
                        : "r"(a[mt][0]), "r"(a[mt][1]), "r"(a[mt][2]), "r"(a[mt][3]),
                          "r"(b[nt][0]), "r"(b[nt][1]));
                }
        }
        __syncthreads();   // compute(tt) done everywhere; B(tt) buffer may be refilled

        // ---- epilogue: d^2 + pos/neg reduction (registers only) ----
        float sj[16]; int lj[16];
#pragma unroll
        for (int nt = 0; nt < 8; nt++)
#pragma unroll
            for (int u = 0; u < 2; u++) {
                int c = wn * 64 + nt * 8 + 2 * tg + u;
                int j = jbase + tt * TILE + c;
                sj[nt * 2 + u] = g_sq[j];
                lj[nt * 2 + u] = g_lab[j];
            }
#pragma unroll
        for (int mt = 0; mt < 2; mt++)
#pragma unroll
            for (int h = 0; h < 2; h++) {
                const int ridx = mt * 2 + h;
                float si = sI[ridx];
                int   li = lI[ridx];
                float p = pm[ridx], n = nm[ridx];
#pragma unroll
                for (int nt = 0; nt < 8; nt++)
#pragma unroll
                    for (int u = 0; u < 2; u++) {
                        float d2 = fmaf(-2.0f, acc[mt][nt][h * 2 + u], si + sj[nt * 2 + u]);
                        d2 = fmaxf(d2, 0.0f);
                        if (li == lj[nt * 2 + u]) p = fmaxf(p, d2);
                        else                      n = fminf(n, d2);
                    }
                pm[ridx] = p; nm[ridx] = n;
            }
    }

    // ---- merge: reduce over the 4 lanes of each group, then atomics ----
#pragma unroll
    for (int ridx = 0; ridx < 4; ridx++) {
        float p = pm[ridx], n = nm[ridx];
        p = fmaxf(p, __shfl_xor_sync(0xffffffffu, p, 1));
        p = fmaxf(p, __shfl_xor_sync(0xffffffffu, p, 2));
        n = fminf(n, __shfl_xor_sync(0xffffffffu, n, 1));
        n = fminf(n, __shfl_xor_sync(0xffffffffu, n, 2));
        if (tg == 0) {
            int row = i0 + wm * 32 + (ridx >> 1) * 16 + (ridx & 1) * 8 + g;
            atomicMax(&g_pos[row], __float_as_int(p));
            atomicMin(&g_neg[row], __float_as_int(n));
        }
    }
}

// ---------------------------------------------------------------------------
// 3) finalize: mean(relu(sqrt(pos) - sqrt(neg) + margin))
// ---------------------------------------------------------------------------
__global__ void k_final(const float* __restrict__ margin, float* __restrict__ out) {
    __shared__ float red[256];
    float m = *margin;
    float sum = 0.0f;
    for (int i = threadIdx.x; i < N; i += 256) {
        float p = sqrtf(__int_as_float(g_pos[i]));
        float n = sqrtf(__int_as_float(g_neg[i]));
        sum += fmaxf(p - n + m, 0.0f);
    }
    red[threadIdx.x] = sum;
    __syncthreads();
#pragma unroll
    for (int s = 128; s > 0; s >>= 1) {
        if (threadIdx.x < s) red[threadIdx.x] += red[threadIdx.x + s];
        __syncthreads();
    }
    if (threadIdx.x == 0) out[0] = red[0] / (float)N;
}

// ---------------------------------------------------------------------------
extern "C" void kernel_launch(void* const* d_in, const int* in_sizes, int n_in,
                              void* d_out, int out_size) {
    const float* emb    = (const float*)d_in[0];
    const int*   lab32  = (const int*)d_in[1];
    const float* margin = (const float*)d_in[2];
    float*       out    = (float*)d_out;

    cudaFuncSetAttribute(k_main, cudaFuncAttributeMaxDynamicSharedMemorySize, SMEM_BYTES);

    k_labels<<<N / 256, 256>>>(lab32);
    k_prep<<<N / 8, 256>>>(emb);
    k_main<<<dim3(N / TILE, 2), NT, SMEM_BYTES>>>();
    k_final<<<1, 256>>>(margin, out);
}